// round 15
// baseline (speedup 1.0000x reference)
#include <cuda_runtime.h>
#include <cuda_bf16.h>
#include <math.h>
#include <stdint.h>

// Eikonal loss: persistent blocks, double-buffered cp.async.bulk pipeline,
// small tiles (8 rows) to keep 5 blocks/SM resident. Contiguous strip chunks
// per block for hot-L2 halo reuse. (B,1,H,W)=(64,1,512,512) fp32 -> scalar.

#define H 512
#define W 512
#define TROWS 8
#define PROWS (TROWS + 2)
#define SPI   (H / TROWS)            // strips per image = 64
#define TILE_F (PROWS * W)
#define TILE_BYTES (TILE_F * 4)      // 20480
#define THREADS 256
#define PBLOCKS 740                  // 148 SMs * 5
#define MAX_BLOCKS 4096

__device__ float2 g_part[MAX_BLOCKS];
__device__ unsigned int g_ticket;    // zero-init at load; last block resets it

__device__ __forceinline__ float sqrt_approx(float x) {
    float r;
    asm("sqrt.approx.f32 %0, %1;" : "=f"(r) : "f"(x));
    return r;
}

__device__ __forceinline__ uint32_t smem_u32(const void* p) {
    uint32_t a;
    asm("{ .reg .u64 t; cvta.to.shared.u64 t, %1; cvt.u32.u64 %0, t; }" : "=r"(a) : "l"(p));
    return a;
}

__device__ __forceinline__ void bulk_cp(uint32_t sdst, const float* src,
                                        uint32_t bytes, uint32_t mbar) {
    asm volatile(
        "cp.async.bulk.shared::cta.global.mbarrier::complete_tx::bytes [%0], [%1], %2, [%3];"
        :: "r"(sdst), "l"(src), "r"(bytes), "r"(mbar) : "memory");
}

// tid0: stage pred rows y-1..y+8 (edge-clamped) of strip s into a buffer.
__device__ __forceinline__ void issue_copy(const float* __restrict__ pred,
                                           int s, uint32_t sdst, uint32_t mbar) {
    const int b = s >> 6;                    // 64 strips per image
    const int y = (s & (SPI - 1)) * TROWS;
    const float* p = pred + (size_t)b * (H * W);
    asm volatile("mbarrier.arrive.expect_tx.shared.b64 _, [%0], %1;"
                 :: "r"(mbar), "r"((uint32_t)TILE_BYTES) : "memory");
    if (y > 0 && y + TROWS < H) {
        bulk_cp(sdst, p + (size_t)(y - 1) * W, TILE_BYTES, mbar);
    } else if (y == 0) {
        bulk_cp(sdst, p, W * 4, mbar);                                      // dup row 0
        bulk_cp(sdst + W * 4, p, (PROWS - 1) * W * 4, mbar);                // rows 0..8
    } else {
        bulk_cp(sdst, p + (size_t)(y - 1) * W, (PROWS - 1) * W * 4, mbar);  // rows y-1..510
        bulk_cp(sdst + (PROWS - 1) * W * 4, p + (size_t)(H - 1) * W, W * 4, mbar); // dup 511
    }
}

__device__ __forceinline__ void mbar_wait(uint32_t mbar, uint32_t parity) {
    asm volatile(
        "{\n\t.reg .pred q;\n\t"
        "WL_%=:\n\t"
        "mbarrier.try_wait.parity.acquire.cta.shared::cta.b64 q, [%0], %1, 0x989680;\n\t"
        "@q bra.uni WD_%=;\n\t"
        "bra.uni WL_%=;\n\t"
        "WD_%=:\n\t}"
        :: "r"(mbar), "r"(parity) : "memory");
}

// Row features (UNSCALED) from an SMEM row.
__device__ __forceinline__ void row_sd_s(const float* __restrict__ sp_row,
                                         int x, int lane,
                                         float* __restrict__ S,
                                         float* __restrict__ D) {
    float4 v = *(const float4*)(sp_row + x);
    float wl = __shfl_up_sync(0xFFFFFFFFu, v.w, 1);
    float wr = __shfl_down_sync(0xFFFFFFFFu, v.x, 1);
    if (lane == 0)  wl = (x == 0)     ? v.x : sp_row[x - 1];
    if (lane == 31) wr = (x + 4 >= W) ? v.w : sp_row[x + 4];
    D[0] = v.y - wl;
    D[1] = v.z - v.x;
    D[2] = v.w - v.y;
    D[3] = wr  - v.z;
    S[0] = fmaf(2.0f, v.x, wl  + v.y);
    S[1] = fmaf(2.0f, v.y, v.x + v.z);
    S[2] = fmaf(2.0f, v.z, v.y + v.w);
    S[3] = fmaf(2.0f, v.w, v.z + wr );
}

// mag = sqrt(gx_u^2 + gy_u^2 + 6.4e-7) * 0.125
__device__ __forceinline__ void out_row(const float* S0, const float* S2,
                                        const float* D0, const float* D1, const float* D2,
                                        float4 rr, float& lsum, int& lcnt) {
    const float rv[4] = {rr.x, rr.y, rr.z, rr.w};
    #pragma unroll
    for (int j = 0; j < 4; j++) {
        float gx = fmaf(2.0f, D1[j], D0[j] + D2[j]);
        float gy = S2[j] - S0[j];
        float g2 = fmaf(gx, gx, fmaf(gy, gy, 6.4e-7f));
        float viol = fabsf(fmaf(sqrt_approx(g2), 0.125f, -1.0f));
        if (rv[j] > 0.5f) {
            lsum += viol;
            lcnt++;
        }
    }
}

__global__ void __launch_bounds__(THREADS, 5) eik_fused_kernel(
    const float* __restrict__ pred,
    const float* __restrict__ reach,
    float* __restrict__ out,
    int nStrips, int nBlocks)
{
    __shared__ __align__(16) float s_buf[2 * TILE_F];   // 40960 B
    __shared__ __align__(8)  uint64_t s_mbar[2];
    __shared__ float s_sum[8];
    __shared__ float s_cnt[8];
    __shared__ bool s_last;

    const int tid  = threadIdx.x;
    const int lane = tid & 31;
    const int G    = gridDim.x;

    const uint32_t mb[2] = {smem_u32(&s_mbar[0]), smem_u32(&s_mbar[1])};
    const uint32_t sd[2] = {smem_u32(s_buf), smem_u32(s_buf) + TILE_BYTES};

    // contiguous strip chunk for this block
    const int per = nStrips / G;
    const int rem = nStrips - per * G;
    const int bid = blockIdx.x;
    const int s0  = bid * per + ((bid < rem) ? bid : rem);
    const int cnt = per + (bid < rem ? 1 : 0);

    if (tid == 0) {
        asm volatile("mbarrier.init.shared.b64 [%0], 1;" :: "r"(mb[0]) : "memory");
        asm volatile("mbarrier.init.shared.b64 [%0], 1;" :: "r"(mb[1]) : "memory");
        // fence init before async proxy use, then start first copy immediately
        asm volatile("fence.proxy.async.shared::cta;" ::: "memory");
        if (cnt > 0) issue_copy(pred, s0, sd[0], mb[0]);
    }
    __syncthreads();   // init visible to all waiters

    // compute decomposition: thread = 4 cols x 4 rows
    const int cg   = tid & 127;
    const int half = tid >> 7;
    const int x    = cg * 4;
    const int o0   = half * 4;       // local first output row

    float lsum = 0.0f;
    int   lcnt = 0;

    for (int n = 0; n < cnt; n++) {
        const int s = s0 + n;
        const int cur = n & 1;

        // issue next strip's copy into the other buffer
        if (n + 1 < cnt && tid == 0)
            issue_copy(pred, s + 1, sd[cur ^ 1], mb[cur ^ 1]);

        // prefetch first reach rows while waiting (independent of SMEM)
        const int b = s >> 6;
        const int y = (s & (SPI - 1)) * TROWS;
        const float* r = reach + (size_t)b * (H * W);
        float4 rq[2];
        rq[0] = __ldcs((const float4*)(r + (size_t)(y + o0 + 0) * W + x));
        rq[1] = __ldcs((const float4*)(r + (size_t)(y + o0 + 1) * W + x));

        mbar_wait(mb[cur], (n >> 1) & 1);

        const float* sp = s_buf + cur * TILE_F;

        float S[3][4], D[3][4];
        row_sd_s(sp + (o0 + 0) * W, x, lane, S[0], D[0]);
        row_sd_s(sp + (o0 + 1) * W, x, lane, S[1], D[1]);

        #pragma unroll
        for (int i = 0; i < 4; i++) {
            row_sd_s(sp + (o0 + i + 2) * W, x, lane, S[(i + 2) % 3], D[(i + 2) % 3]);
            float4 rr = rq[i & 1];
            if (i < 2)
                rq[i & 1] = __ldcs((const float4*)(r + (size_t)(y + o0 + i + 2) * W + x));
            out_row(S[i % 3], S[(i + 2) % 3], D[i % 3], D[(i + 1) % 3], D[(i + 2) % 3],
                    rr, lsum, lcnt);
        }
        __syncthreads();   // buffer reusable
    }

    // ---- block reduction (8 warps) ----
    float fcnt = (float)lcnt;
    #pragma unroll
    for (int off = 16; off > 0; off >>= 1) {
        lsum += __shfl_down_sync(0xFFFFFFFFu, lsum, off);
        fcnt += __shfl_down_sync(0xFFFFFFFFu, fcnt, off);
    }
    const int wid = tid >> 5;
    if (lane == 0) { s_sum[wid] = lsum; s_cnt[wid] = fcnt; }
    __syncthreads();

    if (wid == 0) {
        lsum = (lane < 8) ? s_sum[lane] : 0.0f;
        fcnt = (lane < 8) ? s_cnt[lane] : 0.0f;
        #pragma unroll
        for (int off = 4; off > 0; off >>= 1) {
            lsum += __shfl_down_sync(0xFFFFFFFFu, lsum, off);
            fcnt += __shfl_down_sync(0xFFFFFFFFu, fcnt, off);
        }
        if (lane == 0) {
            g_part[blockIdx.x] = make_float2(lsum, fcnt);
            __threadfence();
            unsigned int prev = atomicAdd(&g_ticket, 1u);
            s_last = (prev == (unsigned int)(nBlocks - 1));
        }
    }
    __syncthreads();

    if (s_last) {
        float fs = 0.0f, fc = 0.0f;
        for (int i = tid; i < nBlocks; i += THREADS) {
            float2 v2 = g_part[i];
            fs += v2.x;
            fc += v2.y;
        }
        #pragma unroll
        for (int off = 16; off > 0; off >>= 1) {
            fs += __shfl_down_sync(0xFFFFFFFFu, fs, off);
            fc += __shfl_down_sync(0xFFFFFFFFu, fc, off);
        }
        if (lane == 0) { s_sum[wid] = fs; s_cnt[wid] = fc; }
        __syncthreads();
        if (tid == 0) {
            fs = 0.0f; fc = 0.0f;
            #pragma unroll
            for (int i = 0; i < 8; i++) { fs += s_sum[i]; fc += s_cnt[i]; }
            out[0] = fs / fmaxf(fc, 1.0f);
            g_ticket = 0;   // reset for next graph replay
        }
    }
}

extern "C" void kernel_launch(void* const* d_in, const int* in_sizes, int n_in,
                              void* d_out, int out_size) {
    const float* pred  = (const float*)d_in[0];
    const float* reach = (const float*)d_in[1];
    float* out = (float*)d_out;

    const int total   = in_sizes[0];            // B*H*W
    const int nStrips = total / (W * TROWS);    // 4096 for B=64

    int blocks = PBLOCKS;
    if (blocks > nStrips) blocks = nStrips;

    eik_fused_kernel<<<blocks, THREADS>>>(pred, reach, out, nStrips, blocks);
}

// round 16
// speedup vs baseline: 1.5588x; 1.5588x over previous
#include <cuda_runtime.h>
#include <cuda_bf16.h>
#include <math.h>
#include <stdint.h>

// Eikonal loss, single fused kernel with cp.async.bulk SMEM staging of pred.
// Block = 16 output rows x 512 cols. Pred rows y-1..y+16 bulk-copied to SMEM
// (async proxy, mbarrier). Reach prefetched (LDG.cs) BEFORE the tile wait so
// its latency overlaps the copy. Compute reads SMEM, rolling 3-row ring.
// (B,1,H,W) = (64,1,512,512) fp32 -> 1 fp32 scalar.

#define H 512
#define W 512
#define TROWS 16
#define PROWS (TROWS + 2)
#define THREADS 256
#define MAX_BLOCKS 16384

__device__ float2 g_part[MAX_BLOCKS];
__device__ unsigned int g_ticket;   // zero-init at load; last block resets it

__device__ __forceinline__ float sqrt_approx(float x) {
    float r;
    asm("sqrt.approx.f32 %0, %1;" : "=f"(r) : "f"(x));
    return r;
}

__device__ __forceinline__ uint32_t smem_u32(const void* p) {
    uint32_t a;
    asm("{ .reg .u64 t; cvta.to.shared.u64 t, %1; cvt.u32.u64 %0, t; }" : "=r"(a) : "l"(p));
    return a;
}

// Row features (UNSCALED) from an SMEM row: D = horiz central diff, S = [1,2,1] sum.
__device__ __forceinline__ void row_sd_s(const float* __restrict__ sp_row,
                                         int x, int lane,
                                         float* __restrict__ S,
                                         float* __restrict__ D) {
    float4 v = *(const float4*)(sp_row + x);
    float wl = __shfl_up_sync(0xFFFFFFFFu, v.w, 1);
    float wr = __shfl_down_sync(0xFFFFFFFFu, v.x, 1);
    if (lane == 0)  wl = (x == 0)     ? v.x : sp_row[x - 1];
    if (lane == 31) wr = (x + 4 >= W) ? v.w : sp_row[x + 4];
    D[0] = v.y - wl;
    D[1] = v.z - v.x;
    D[2] = v.w - v.y;
    D[3] = wr  - v.z;
    S[0] = fmaf(2.0f, v.x, wl  + v.y);
    S[1] = fmaf(2.0f, v.y, v.x + v.z);
    S[2] = fmaf(2.0f, v.z, v.y + v.w);
    S[3] = fmaf(2.0f, v.w, v.z + wr );
}

// mag = sqrt(gx_u^2 + gy_u^2 + 6.4e-7) * 0.125 == sqrt((gx_u/8)^2+(gy_u/8)^2+1e-8)
__device__ __forceinline__ void out_row(const float* S0, const float* S2,
                                        const float* D0, const float* D1, const float* D2,
                                        float4 rr, float& lsum, int& lcnt) {
    const float rv[4] = {rr.x, rr.y, rr.z, rr.w};
    #pragma unroll
    for (int j = 0; j < 4; j++) {
        float gx = fmaf(2.0f, D1[j], D0[j] + D2[j]);
        float gy = S2[j] - S0[j];
        float g2 = fmaf(gx, gx, fmaf(gy, gy, 6.4e-7f));
        float viol = fabsf(fmaf(sqrt_approx(g2), 0.125f, -1.0f));
        if (rv[j] > 0.5f) {
            lsum += viol;
            lcnt++;
        }
    }
}

__global__ void __launch_bounds__(THREADS, 5) eik_fused_kernel(
    const float* __restrict__ pred,
    const float* __restrict__ reach,
    float* __restrict__ out,
    int nBlocks)
{
    __shared__ __align__(16) float s_pred[PROWS * W];   // 36864 B
    __shared__ __align__(8)  uint64_t s_mbar;

    const int tid  = threadIdx.x;
    const int lane = tid & 31;

    // block -> (b, strip): 32 strips/image
    const int b     = blockIdx.x >> 5;
    const int strip = blockIdx.x & 31;
    const int y     = strip * TROWS;

    const size_t base = (size_t)b * (H * W);
    const float* p = pred + base;
    const float* r = reach + base;

    const uint32_t mbar = smem_u32(&s_mbar);

    if (tid == 0)
        asm volatile("mbarrier.init.shared.b64 [%0], 1;" :: "r"(mbar) : "memory");
    __syncthreads();

    if (tid == 0) {
        asm volatile("mbarrier.arrive.expect_tx.shared.b64 _, [%0], %1;"
                     :: "r"(mbar), "r"((uint32_t)(PROWS * W * 4)) : "memory");
        const uint32_t sdst = smem_u32(s_pred);
        if (y > 0 && y + TROWS < H) {
            // interior: rows y-1 .. y+16 contiguous — one 36 KB bulk copy
            asm volatile(
                "cp.async.bulk.shared::cta.global.mbarrier::complete_tx::bytes [%0], [%1], %2, [%3];"
                :: "r"(sdst), "l"(p + (size_t)(y - 1) * W),
                   "r"((uint32_t)(PROWS * W * 4)), "r"(mbar) : "memory");
        } else if (y == 0) {
            // row 0 duplicated into slot 0; rows 0..16 into slots 1..17
            asm volatile(
                "cp.async.bulk.shared::cta.global.mbarrier::complete_tx::bytes [%0], [%1], %2, [%3];"
                :: "r"(sdst), "l"(p), "r"((uint32_t)(W * 4)), "r"(mbar) : "memory");
            asm volatile(
                "cp.async.bulk.shared::cta.global.mbarrier::complete_tx::bytes [%0], [%1], %2, [%3];"
                :: "r"(sdst + W * 4), "l"(p),
                   "r"((uint32_t)((PROWS - 1) * W * 4)), "r"(mbar) : "memory");
        } else {
            // bottom: rows y-1..510 into slots 0..16; row 511 duplicated into slot 17
            asm volatile(
                "cp.async.bulk.shared::cta.global.mbarrier::complete_tx::bytes [%0], [%1], %2, [%3];"
                :: "r"(sdst), "l"(p + (size_t)(y - 1) * W),
                   "r"((uint32_t)((PROWS - 1) * W * 4)), "r"(mbar) : "memory");
            asm volatile(
                "cp.async.bulk.shared::cta.global.mbarrier::complete_tx::bytes [%0], [%1], %2, [%3];"
                :: "r"(sdst + (PROWS - 1) * W * 4), "l"(p + (size_t)(H - 1) * W),
                   "r"((uint32_t)(W * 4)), "r"(mbar) : "memory");
        }
    }

    // ---- compute decomposition: thread = 4 cols x 8 rows ----
    const int cg   = tid & 127;       // column group
    const int half = tid >> 7;        // 0/1 -> rows 0-7 / 8-15
    const int x    = cg * 4;
    const int o0   = half * 8;        // first output row (local)

    // prefetch reach BEFORE the tile wait — LDG latency overlaps copy arrival
    float4 rq[2];
    rq[0] = __ldcs((const float4*)(r + (size_t)(y + o0 + 0) * W + x));
    rq[1] = __ldcs((const float4*)(r + (size_t)(y + o0 + 1) * W + x));

    // all threads wait for the tile (acquire)
    {
        uint32_t done;
        asm volatile(
            "{\n\t.reg .pred q;\n\t"
            "mbarrier.try_wait.parity.acquire.cta.shared::cta.b64 q, [%1], 0;\n\t"
            "selp.b32 %0, 1, 0, q;\n\t}"
            : "=r"(done) : "r"(mbar) : "memory");
        if (!done) {
            asm volatile(
                "{\n\t.reg .pred q;\n\t"
                "WL_%=:\n\t"
                "mbarrier.try_wait.parity.acquire.cta.shared::cta.b64 q, [%0], 0, 0x989680;\n\t"
                "@q bra.uni WD_%=;\n\t"
                "bra.uni WL_%=;\n\t"
                "WD_%=:\n\t}"
                :: "r"(mbar) : "memory");
        }
    }

    float S[3][4], D[3][4];
    row_sd_s(s_pred + (o0 + 0) * W, x, lane, S[0], D[0]);
    row_sd_s(s_pred + (o0 + 1) * W, x, lane, S[1], D[1]);

    float lsum = 0.0f;
    int   lcnt = 0;

    #pragma unroll
    for (int i = 0; i < 8; i++) {
        row_sd_s(s_pred + (o0 + i + 2) * W, x, lane, S[(i + 2) % 3], D[(i + 2) % 3]);
        float4 rr = rq[i & 1];
        if (i < 6)
            rq[i & 1] = __ldcs((const float4*)(r + (size_t)(y + o0 + i + 2) * W + x));
        out_row(S[i % 3], S[(i + 2) % 3], D[i % 3], D[(i + 1) % 3], D[(i + 2) % 3],
                rr, lsum, lcnt);
    }

    // ---- block reduction (8 warps) ----
    float fcnt = (float)lcnt;
    #pragma unroll
    for (int off = 16; off > 0; off >>= 1) {
        lsum += __shfl_down_sync(0xFFFFFFFFu, lsum, off);
        fcnt += __shfl_down_sync(0xFFFFFFFFu, fcnt, off);
    }

    __shared__ float s_sum[8];
    __shared__ float s_cnt[8];
    const int wid = tid >> 5;
    if (lane == 0) { s_sum[wid] = lsum; s_cnt[wid] = fcnt; }
    __syncthreads();

    __shared__ bool s_last;
    if (wid == 0) {
        lsum = (lane < 8) ? s_sum[lane] : 0.0f;
        fcnt = (lane < 8) ? s_cnt[lane] : 0.0f;
        #pragma unroll
        for (int off = 4; off > 0; off >>= 1) {
            lsum += __shfl_down_sync(0xFFFFFFFFu, lsum, off);
            fcnt += __shfl_down_sync(0xFFFFFFFFu, fcnt, off);
        }
        if (lane == 0) {
            g_part[blockIdx.x] = make_float2(lsum, fcnt);
            __threadfence();
            unsigned int prev = atomicAdd(&g_ticket, 1u);
            s_last = (prev == (unsigned int)(nBlocks - 1));
        }
    }
    __syncthreads();

    // ---- last block: reduce partials, write output, reset ticket ----
    if (s_last) {
        float fs = 0.0f, fc = 0.0f;
        for (int i = tid; i < nBlocks; i += THREADS) {
            float2 v2 = g_part[i];
            fs += v2.x;
            fc += v2.y;
        }
        #pragma unroll
        for (int off = 16; off > 0; off >>= 1) {
            fs += __shfl_down_sync(0xFFFFFFFFu, fs, off);
            fc += __shfl_down_sync(0xFFFFFFFFu, fc, off);
        }
        if (lane == 0) { s_sum[wid] = fs; s_cnt[wid] = fc; }
        __syncthreads();
        if (tid == 0) {
            fs = 0.0f; fc = 0.0f;
            #pragma unroll
            for (int i = 0; i < 8; i++) { fs += s_sum[i]; fc += s_cnt[i]; }
            out[0] = fs / fmaxf(fc, 1.0f);
            g_ticket = 0;   // reset for next graph replay
        }
    }
}

extern "C" void kernel_launch(void* const* d_in, const int* in_sizes, int n_in,
                              void* d_out, int out_size) {
    const float* pred  = (const float*)d_in[0];
    const float* reach = (const float*)d_in[1];
    float* out = (float*)d_out;

    const int total   = in_sizes[0];            // B*H*W
    const int nBlocks = total / (W * TROWS);    // 2048 for B=64

    eik_fused_kernel<<<nBlocks, THREADS>>>(pred, reach, out, nBlocks);
}

// round 17
// speedup vs baseline: 1.7465x; 1.1204x over previous
#include <cuda_runtime.h>
#include <cuda_bf16.h>
#include <math.h>
#include <stdint.h>

// Eikonal loss, single fused kernel with cp.async.bulk SMEM staging of pred.
// Block = 16 output rows x 512 cols. Pred rows y-1..y+16 bulk-copied to SMEM
// (async proxy, mbarrier). Reach prefetched (LDG.cs) BEFORE the tile wait.
// Halos read directly from SMEM (clamped offsets precomputed) — no shuffles.
// (B,1,H,W) = (64,1,512,512) fp32 -> 1 fp32 scalar.

#define H 512
#define W 512
#define TROWS 16
#define PROWS (TROWS + 2)
#define THREADS 256
#define MAX_BLOCKS 16384

__device__ float2 g_part[MAX_BLOCKS];
__device__ unsigned int g_ticket;   // zero-init at load; last block resets it

__device__ __forceinline__ float sqrt_approx(float x) {
    float r;
    asm("sqrt.approx.f32 %0, %1;" : "=f"(r) : "f"(x));
    return r;
}

__device__ __forceinline__ uint32_t smem_u32(const void* p) {
    uint32_t a;
    asm("{ .reg .u64 t; cvta.to.shared.u64 t, %1; cvt.u32.u64 %0, t; }" : "=r"(a) : "l"(p));
    return a;
}

// Row features (UNSCALED) from an SMEM row: D = horiz central diff, S = [1,2,1] sum.
// Halos via direct (pre-clamped) scalar LDS — independent of the float4 load.
__device__ __forceinline__ void row_sd_s(const float* __restrict__ sp_row,
                                         int x, int xl, int xr,
                                         float* __restrict__ S,
                                         float* __restrict__ D) {
    float4 v = *(const float4*)(sp_row + x);
    float wl = sp_row[xl];
    float wr = sp_row[xr];
    D[0] = v.y - wl;
    D[1] = v.z - v.x;
    D[2] = v.w - v.y;
    D[3] = wr  - v.z;
    S[0] = fmaf(2.0f, v.x, wl  + v.y);
    S[1] = fmaf(2.0f, v.y, v.x + v.z);
    S[2] = fmaf(2.0f, v.z, v.y + v.w);
    S[3] = fmaf(2.0f, v.w, v.z + wr );
}

// mag = sqrt(gx_u^2 + gy_u^2 + 6.4e-7) * 0.125 == sqrt((gx_u/8)^2+(gy_u/8)^2+1e-8)
__device__ __forceinline__ void out_row(const float* S0, const float* S2,
                                        const float* D0, const float* D1, const float* D2,
                                        float4 rr, float& lsum, int& lcnt) {
    const float rv[4] = {rr.x, rr.y, rr.z, rr.w};
    #pragma unroll
    for (int j = 0; j < 4; j++) {
        float gx = fmaf(2.0f, D1[j], D0[j] + D2[j]);
        float gy = S2[j] - S0[j];
        float g2 = fmaf(gx, gx, fmaf(gy, gy, 6.4e-7f));
        float viol = fabsf(fmaf(sqrt_approx(g2), 0.125f, -1.0f));
        if (rv[j] > 0.5f) {
            lsum += viol;
            lcnt++;
        }
    }
}

__global__ void __launch_bounds__(THREADS, 5) eik_fused_kernel(
    const float* __restrict__ pred,
    const float* __restrict__ reach,
    float* __restrict__ out,
    int nBlocks)
{
    __shared__ __align__(16) float s_pred[PROWS * W];   // 36864 B
    __shared__ __align__(8)  uint64_t s_mbar;

    const int tid  = threadIdx.x;
    const int lane = tid & 31;

    // block -> (b, strip): 32 strips/image
    const int b     = blockIdx.x >> 5;
    const int strip = blockIdx.x & 31;
    const int y     = strip * TROWS;

    const size_t base = (size_t)b * (H * W);
    const float* p = pred + base;
    const float* r = reach + base;

    const uint32_t mbar = smem_u32(&s_mbar);

    if (tid == 0)
        asm volatile("mbarrier.init.shared.b64 [%0], 1;" :: "r"(mbar) : "memory");
    __syncthreads();

    if (tid == 0) {
        asm volatile("mbarrier.arrive.expect_tx.shared.b64 _, [%0], %1;"
                     :: "r"(mbar), "r"((uint32_t)(PROWS * W * 4)) : "memory");
        const uint32_t sdst = smem_u32(s_pred);
        if (y > 0 && y + TROWS < H) {
            // interior: rows y-1 .. y+16 contiguous — one 36 KB bulk copy
            asm volatile(
                "cp.async.bulk.shared::cta.global.mbarrier::complete_tx::bytes [%0], [%1], %2, [%3];"
                :: "r"(sdst), "l"(p + (size_t)(y - 1) * W),
                   "r"((uint32_t)(PROWS * W * 4)), "r"(mbar) : "memory");
        } else if (y == 0) {
            // row 0 duplicated into slot 0; rows 0..16 into slots 1..17
            asm volatile(
                "cp.async.bulk.shared::cta.global.mbarrier::complete_tx::bytes [%0], [%1], %2, [%3];"
                :: "r"(sdst), "l"(p), "r"((uint32_t)(W * 4)), "r"(mbar) : "memory");
            asm volatile(
                "cp.async.bulk.shared::cta.global.mbarrier::complete_tx::bytes [%0], [%1], %2, [%3];"
                :: "r"(sdst + W * 4), "l"(p),
                   "r"((uint32_t)((PROWS - 1) * W * 4)), "r"(mbar) : "memory");
        } else {
            // bottom: rows y-1..510 into slots 0..16; row 511 duplicated into slot 17
            asm volatile(
                "cp.async.bulk.shared::cta.global.mbarrier::complete_tx::bytes [%0], [%1], %2, [%3];"
                :: "r"(sdst), "l"(p + (size_t)(y - 1) * W),
                   "r"((uint32_t)((PROWS - 1) * W * 4)), "r"(mbar) : "memory");
            asm volatile(
                "cp.async.bulk.shared::cta.global.mbarrier::complete_tx::bytes [%0], [%1], %2, [%3];"
                :: "r"(sdst + (PROWS - 1) * W * 4), "l"(p + (size_t)(H - 1) * W),
                   "r"((uint32_t)(W * 4)), "r"(mbar) : "memory");
        }
    }

    // ---- compute decomposition: thread = 4 cols x 8 rows ----
    const int cg   = tid & 127;       // column group
    const int half = tid >> 7;        // 0/1 -> rows 0-7 / 8-15
    const int x    = cg * 4;
    const int o0   = half * 8;        // first output row (local)
    const int xl   = (x > 0) ? (x - 1) : 0;           // clamped halo columns
    const int xr   = (x + 4 < W) ? (x + 4) : (W - 1);

    // prefetch reach BEFORE the tile wait — LDG latency overlaps copy arrival
    float4 rq[2];
    rq[0] = __ldcs((const float4*)(r + (size_t)(y + o0 + 0) * W + x));
    rq[1] = __ldcs((const float4*)(r + (size_t)(y + o0 + 1) * W + x));

    // all threads wait for the tile (acquire)
    {
        uint32_t done;
        asm volatile(
            "{\n\t.reg .pred q;\n\t"
            "mbarrier.try_wait.parity.acquire.cta.shared::cta.b64 q, [%1], 0;\n\t"
            "selp.b32 %0, 1, 0, q;\n\t}"
            : "=r"(done) : "r"(mbar) : "memory");
        if (!done) {
            asm volatile(
                "{\n\t.reg .pred q;\n\t"
                "WL_%=:\n\t"
                "mbarrier.try_wait.parity.acquire.cta.shared::cta.b64 q, [%0], 0, 0x989680;\n\t"
                "@q bra.uni WD_%=;\n\t"
                "bra.uni WL_%=;\n\t"
                "WD_%=:\n\t}"
                :: "r"(mbar) : "memory");
        }
    }

    float S[3][4], D[3][4];
    row_sd_s(s_pred + (o0 + 0) * W, x, xl, xr, S[0], D[0]);
    row_sd_s(s_pred + (o0 + 1) * W, x, xl, xr, S[1], D[1]);

    float lsum = 0.0f;
    int   lcnt = 0;

    #pragma unroll
    for (int i = 0; i < 8; i++) {
        row_sd_s(s_pred + (o0 + i + 2) * W, x, xl, xr, S[(i + 2) % 3], D[(i + 2) % 3]);
        float4 rr = rq[i & 1];
        if (i < 6)
            rq[i & 1] = __ldcs((const float4*)(r + (size_t)(y + o0 + i + 2) * W + x));
        out_row(S[i % 3], S[(i + 2) % 3], D[i % 3], D[(i + 1) % 3], D[(i + 2) % 3],
                rr, lsum, lcnt);
    }

    // ---- block reduction (8 warps) ----
    float fcnt = (float)lcnt;
    #pragma unroll
    for (int off = 16; off > 0; off >>= 1) {
        lsum += __shfl_down_sync(0xFFFFFFFFu, lsum, off);
        fcnt += __shfl_down_sync(0xFFFFFFFFu, fcnt, off);
    }

    __shared__ float s_sum[8];
    __shared__ float s_cnt[8];
    const int wid = tid >> 5;
    if (lane == 0) { s_sum[wid] = lsum; s_cnt[wid] = fcnt; }
    __syncthreads();

    __shared__ bool s_last;
    if (wid == 0) {
        lsum = (lane < 8) ? s_sum[lane] : 0.0f;
        fcnt = (lane < 8) ? s_cnt[lane] : 0.0f;
        #pragma unroll
        for (int off = 4; off > 0; off >>= 1) {
            lsum += __shfl_down_sync(0xFFFFFFFFu, lsum, off);
            fcnt += __shfl_down_sync(0xFFFFFFFFu, fcnt, off);
        }
        if (lane == 0) {
            g_part[blockIdx.x] = make_float2(lsum, fcnt);
            __threadfence();
            unsigned int prev = atomicAdd(&g_ticket, 1u);
            s_last = (prev == (unsigned int)(nBlocks - 1));
        }
    }
    __syncthreads();

    // ---- last block: reduce partials, write output, reset ticket ----
    if (s_last) {
        float fs = 0.0f, fc = 0.0f;
        for (int i = tid; i < nBlocks; i += THREADS) {
            float2 v2 = g_part[i];
            fs += v2.x;
            fc += v2.y;
        }
        #pragma unroll
        for (int off = 16; off > 0; off >>= 1) {
            fs += __shfl_down_sync(0xFFFFFFFFu, fs, off);
            fc += __shfl_down_sync(0xFFFFFFFFu, fc, off);
        }
        if (lane == 0) { s_sum[wid] = fs; s_cnt[wid] = fc; }
        __syncthreads();
        if (tid == 0) {
            fs = 0.0f; fc = 0.0f;
            #pragma unroll
            for (int i = 0; i < 8; i++) { fs += s_sum[i]; fc += s_cnt[i]; }
            out[0] = fs / fmaxf(fc, 1.0f);
            g_ticket = 0;   // reset for next graph replay
        }
    }
}

extern "C" void kernel_launch(void* const* d_in, const int* in_sizes, int n_in,
                              void* d_out, int out_size) {
    const float* pred  = (const float*)d_in[0];
    const float* reach = (const float*)d_in[1];
    float* out = (float*)d_out;

    const int total   = in_sizes[0];            // B*H*W
    const int nBlocks = total / (W * TROWS);    // 2048 for B=64

    eik_fused_kernel<<<nBlocks, THREADS>>>(pred, reach, out, nBlocks);
}